// round 5
// baseline (speedup 1.0000x reference)
#include <cuda_runtime.h>
#include <cstdint>

#define BB 64
#define NN 512
#define DD 64
#define HH 4
#define CC 64
#define NEGS 0.2f

typedef unsigned long long ull;

// Scratch (device globals - no runtime allocation allowed)
__device__ float g_h[BB*NN*HH*CC];     // [b][n][h][c]
__device__ float g_x[BB*NN*DD];        // layer activations
__device__ float g_asrc[BB*HH*NN];     // [b][h][n]
__device__ float g_adst[BB*HH*NN];     // [b][h][n]

// ---- f32x2 helpers -------------------------------------------------------
__device__ __forceinline__ ull packdup(float a) {
    ull r; asm("mov.b64 %0, {%1, %1};" : "=l"(r) : "f"(a)); return r;
}
__device__ __forceinline__ void fma2(ull& d, ull a, ull b) {
    asm("fma.rn.f32x2 %0, %1, %2, %0;" : "+l"(d) : "l"(a), "l"(b));
}
__device__ __forceinline__ float2 unpack2(ull v) {
    float2 r; asm("mov.b64 {%0, %1}, %2;" : "=f"(r.x), "=f"(r.y) : "l"(v));
    return r;
}
__device__ __forceinline__ uint32_t smem_u32(const void* p) {
    uint32_t a;
    asm("{ .reg .u64 t; cvta.to.shared.u64 t, %1; cvt.u32.u64 %0, t; }"
        : "=r"(a) : "l"(p));
    return a;
}
__device__ __forceinline__ void cp_async16(uint32_t dst, const void* src) {
    asm volatile("cp.async.ca.shared.global [%0], [%1], 16;"
                 :: "r"(dst), "l"(src));
}
#define CP_COMMIT() asm volatile("cp.async.commit_group;")
#define CP_WAIT0()  asm volatile("cp.async.wait_group 0;")

// ---------------------------------------------------------------------------
// Kernel 1: h = x @ W^T for one layer, 64x64 tile, one head per blockIdx.y.
// Epilogue computes a_src/a_dst per node.
// ---------------------------------------------------------------------------
__global__ __launch_bounds__(256) void k_lin(
    const float* __restrict__ x, const float* __restrict__ W,
    const float* __restrict__ attS, const float* __restrict__ attD)
{
    __shared__ float s_x[64][68];   // transposed [k][row]
    __shared__ float s_w[64][68];   // transposed [k][col]
    const int t    = threadIdx.x;
    const int row0 = blockIdx.x * 64;
    const int hh   = blockIdx.y;

    {
        const int li = t >> 2;
        const int c4 = t & 3;
        const float4* x4 = (const float4*)x;
        const float4* w4 = (const float4*)W;
        #pragma unroll
        for (int q = 0; q < 4; q++) {
            int kc = c4 + q * 4;
            float4 v = x4[(row0 + li) * 16 + kc];
            s_x[kc*4+0][li] = v.x; s_x[kc*4+1][li] = v.y;
            s_x[kc*4+2][li] = v.z; s_x[kc*4+3][li] = v.w;
            float4 u = w4[(hh * 64 + li) * 16 + kc];
            s_w[kc*4+0][li] = u.x; s_w[kc*4+1][li] = u.y;
            s_w[kc*4+2][li] = u.z; s_w[kc*4+3][li] = u.w;
        }
    }
    __syncthreads();

    const int tx = t & 15, ty = t >> 4;
    float acc[4][4] = {};
    #pragma unroll
    for (int k = 0; k < 64; k++) {
        float4 a = *(const float4*)&s_x[k][ty * 4];
        float4 b = *(const float4*)&s_w[k][tx * 4];
        float av[4] = {a.x, a.y, a.z, a.w};
        float bv[4] = {b.x, b.y, b.z, b.w};
        #pragma unroll
        for (int i = 0; i < 4; i++)
            #pragma unroll
            for (int c = 0; c < 4; c++)
                acc[i][c] += av[i] * bv[c];
    }

    #pragma unroll
    for (int i = 0; i < 4; i++) {
        *(float4*)&g_h[(row0 + ty * 4 + i) * 256 + hh * 64 + tx * 4] =
            make_float4(acc[i][0], acc[i][1], acc[i][2], acc[i][3]);
    }

    float aSv[4], aDv[4];
    #pragma unroll
    for (int c = 0; c < 4; c++) {
        aSv[c] = attS[hh * 64 + tx * 4 + c];
        aDv[c] = attD[hh * 64 + tx * 4 + c];
    }
    #pragma unroll
    for (int i = 0; i < 4; i++) {
        float ps = 0.f, pd = 0.f;
        #pragma unroll
        for (int c = 0; c < 4; c++) { ps += acc[i][c] * aSv[c]; pd += acc[i][c] * aDv[c]; }
        #pragma unroll
        for (int off = 8; off > 0; off >>= 1) {
            ps += __shfl_xor_sync(0xffffffffu, ps, off);
            pd += __shfl_xor_sync(0xffffffffu, pd, off);
        }
        if (tx == 0) {
            int ng = row0 + ty * 4 + i;
            int b = ng >> 9, n = ng & 511;
            g_asrc[(b * HH + hh) * NN + n] = ps;
            g_adst[(b * HH + hh) * NN + n] = pd;
        }
    }
}

// ---------------------------------------------------------------------------
// Kernel 2: fused attention aggregation, no-max softmax, deferred norm.
//   128 threads/block, tile 64 i x 64 c, grid (64 b, 8 i-tiles) = 512 blocks
//   -> 3-4 blocks/SM resident (43.5 KB smem). Microtile 4i x 8c, f32x2 FMA.
//   cp.async stages the h tile while the exp/gen phase runs.
// smem (floats): asrc[2048] | adst[256] | den[128] | s_h[64][68] | s_w[64][64]
// ---------------------------------------------------------------------------
extern __shared__ float smem[];

__global__ __launch_bounds__(128) void k_agg(const float* __restrict__ cb)
{
    float* s_asrc = smem;                              // [4][512]
    float* s_adst = smem + 2048;                       // [4][64]
    float* s_den  = smem + 2304;                       // [2][64]
    float (*s_h)[68] = (float(*)[68])(smem + 2432);    // [64][68]
    float (*s_w)[64] = (float(*)[64])(smem + 6784);    // [64 j][64 i]
    // total 10880 floats = 43520 B

    const int t  = threadIdx.x;
    const int b  = blockIdx.x;
    const int i0 = blockIdx.y * 64;

    // stage a_src [4][512]
    {
        const float4* src = (const float4*)(g_asrc + b * HH * NN);
        float4* dst = (float4*)s_asrc;
        dst[t]       = src[t];
        dst[t + 128] = src[t + 128];
        dst[t + 256] = src[t + 256];
        dst[t + 384] = src[t + 384];
    }
    // stage a_dst [4][64]
    if (t < 64) {
        #pragma unroll
        for (int h = 0; h < HH; h++)
            s_adst[h * 64 + t] = g_adst[(b * HH + h) * NN + i0 + t];
    }
    __syncthreads();

    const int tx = t & 7;            // c group (8 cols)
    const int ty = t >> 3;           // i group (4 rows), 0..15
    const int il = t & 63;           // generator's owned i
    const int jh = t >> 6;           // generator's j half (0/1)

    // cp.async staging geometry: thread covers row jl = t>>1, 32-col half
    const int sjl = t >> 1;
    const int sc0 = (t & 1) * 32;
    const uint32_t s_h_addr = smem_u32(&s_h[sjl][sc0]);

    ull accT[16], accH[16];
    #pragma unroll
    for (int k = 0; k < 16; k++) { accT[k] = 0ull; accH[k] = 0ull; }

    for (int h = 0; h < HH; h++) {
        const float d_t = s_adst[h * 64 + il];
        const float* asr = s_asrc + h * 512;
        float den = 0.f;

        for (int jt = 0; jt < 8; jt++) {
            const int j0 = jt * 64;
            __syncthreads();   // previous tile fully consumed

            // Issue async h-tile copy first (overlaps with gen phase)
            {
                const float* gp = g_h + ((b * NN + j0 + sjl) * HH + h) * CC + sc0;
                #pragma unroll
                for (int q = 0; q < 8; q++)
                    cp_async16(s_h_addr + q * 16, gp + q * 4);
                CP_COMMIT();
            }
            // Generate w half-tile [32 j][64 i]; also accumulate partial den
            {
                const float* aj = asr + j0 + jh * 32;
                #pragma unroll 8
                for (int q = 0; q < 32; q++) {
                    float e = d_t + aj[q];
                    e = fmaxf(e, NEGS * e);
                    float w = __expf(e);
                    s_w[jh * 32 + q][il] = w;
                    den += w;
                }
            }
            CP_WAIT0();
            __syncthreads();

            // Accumulate: acc[i][c] += w[i] * h[c]
            #pragma unroll 4
            for (int jl = 0; jl < 64; jl++) {
                float4 A = *(const float4*)&s_w[jl][ty * 4];
                ulonglong2 H0 = *(const ulonglong2*)&s_h[jl][tx * 8];
                ulonglong2 H1 = *(const ulonglong2*)&s_h[jl][tx * 8 + 4];
                ull hp4[4] = {H0.x, H0.y, H1.x, H1.y};
                float av[4] = {A.x, A.y, A.z, A.w};
                #pragma unroll
                for (int i = 0; i < 4; i++) {
                    ull ad = packdup(av[i]);
                    #pragma unroll
                    for (int c2 = 0; c2 < 4; c2++)
                        fma2(accH[i * 4 + c2], ad, hp4[c2]);
                }
            }
        }

        // publish partial denominators [jh][il] = s_den[t]
        __syncthreads();
        s_den[t] = den;
        __syncthreads();

        // head fold: accT += (0.25/den_i) * accH ; reset accH
        #pragma unroll
        for (int i = 0; i < 4; i++) {
            int ii = ty * 4 + i;
            float sc = 0.25f * __frcp_rn(s_den[ii] + s_den[64 + ii]);
            ull sd = packdup(sc);
            #pragma unroll
            for (int c2 = 0; c2 < 4; c2++) {
                fma2(accT[i * 4 + c2], sd, accH[i * 4 + c2]);
                accH[i * 4 + c2] = 0ull;
            }
        }
    }

    // Epilogue: bias + relu -> g_x
    float bias[8];
    #pragma unroll
    for (int c = 0; c < 8; c++) bias[c] = cb[tx * 8 + c];
    #pragma unroll
    for (int i = 0; i < 4; i++) {
        float v[8];
        #pragma unroll
        for (int c2 = 0; c2 < 4; c2++) {
            float2 f = unpack2(accT[i * 4 + c2]);
            v[c2 * 2 + 0] = fmaxf(f.x + bias[c2 * 2 + 0], 0.f);
            v[c2 * 2 + 1] = fmaxf(f.y + bias[c2 * 2 + 1], 0.f);
        }
        float* xp = g_x + (b * NN + i0 + ty * 4 + i) * DD + tx * 8;
        *(float4*)xp       = make_float4(v[0], v[1], v[2], v[3]);
        *(float4*)(xp + 4) = make_float4(v[4], v[5], v[6], v[7]);
    }
}

// ---------------------------------------------------------------------------
// Kernel 3: node-mean pooling + readout linear.
// ---------------------------------------------------------------------------
__global__ __launch_bounds__(256) void k_read(
    const float* __restrict__ rw, const float* __restrict__ rb,
    float* __restrict__ out)
{
    __shared__ float s_part[4][64];
    __shared__ float s_pool[64];
    const int t = threadIdx.x;
    const int b = blockIdx.x;
    const int c = t & 63, part = t >> 6;
    float s = 0.f;
    for (int i = part; i < NN; i += 4)
        s += g_x[(b * NN + i) * DD + c];
    s_part[part][c] = s;
    __syncthreads();
    if (t < 64)
        s_pool[t] = (s_part[0][t] + s_part[1][t] + s_part[2][t] + s_part[3][t])
                    * (1.0f / NN);
    __syncthreads();
    if (t < 64) {
        float a = rb[t];
        #pragma unroll 8
        for (int c2 = 0; c2 < 64; c2++)
            a += s_pool[c2] * rw[t * 64 + c2];
        out[b * 64 + t] = a;
    }
}

// ---------------------------------------------------------------------------
extern "C" void kernel_launch(void* const* d_in, const int* in_sizes, int n_in,
                              void* d_out, int out_size)
{
    const float* emb = (const float*)d_in[0];
    const float* lin = (const float*)d_in[1];
    const float* aS  = (const float*)d_in[2];
    const float* aD  = (const float*)d_in[3];
    const float* cb  = (const float*)d_in[4];
    const float* rw  = (const float*)d_in[5];
    const float* rb  = (const float*)d_in[6];
    float* out = (float*)d_out;

    float* gx = nullptr;
    cudaGetSymbolAddress((void**)&gx, g_x);
    cudaFuncSetAttribute(k_agg, cudaFuncAttributeMaxDynamicSharedMemorySize, 45056);
    cudaFuncSetAttribute(k_agg, cudaFuncAttributePreferredSharedMemoryCarveout, 100);

    for (int l = 0; l < 3; l++) {
        const float* xin = (l == 0) ? emb : gx;
        k_lin<<<dim3(512, 4), 256>>>(xin, lin + l * 256 * 64,
                                     aS + l * HH * CC, aD + l * HH * CC);
        k_agg<<<dim3(64, 8), 128, 43520>>>(cb + l * CC);
    }
    k_read<<<64, 256>>>(rw, rb, out);
}

// round 6
// speedup vs baseline: 2.6041x; 2.6041x over previous
#include <cuda_runtime.h>
#include <cstdint>

#define BB 64
#define NN 512
#define DD 64
#define HH 4
#define CC 64
#define NEGS 0.2f

// Scratch (device globals - no runtime allocation allowed)
__device__ float g_h[BB*NN*HH*CC];       // [b][n][h*64+c]
__device__ float g_part[BB*HH*NN*CC];    // per-head softmax-agg output
__device__ float g_asrc[BB*HH*NN];       // [b][h][n]
__device__ float g_adst[BB*HH*NN];       // [b][h][n]

// ---------------------------------------------------------------------------
// Kernel 1: h = x @ W^T for one layer, 64x64 tile, one head per blockIdx.y.
// When cbp != null, the input x is formed on the fly from the previous
// layer's per-head partials: x = relu(0.25*sum_h part + cb_prev).
// Epilogue computes a_src/a_dst per node.
// ---------------------------------------------------------------------------
__global__ __launch_bounds__(256) void k_lin(
    const float* __restrict__ x, const float* __restrict__ part,
    const float* __restrict__ W,
    const float* __restrict__ attS, const float* __restrict__ attD,
    const float* __restrict__ cbp)
{
    __shared__ float s_x[64][68];   // transposed [k][row]
    __shared__ float s_w[64][68];   // transposed [k][col]
    const int t    = threadIdx.x;
    const int row0 = blockIdx.x * 64;
    const int hh   = blockIdx.y;

    {
        const int li = t >> 2;
        const int c4 = t & 3;
        const float4* w4 = (const float4*)W;
        #pragma unroll
        for (int q = 0; q < 4; q++) {
            int kc = c4 + q * 4;
            float4 v;
            if (cbp == nullptr) {
                v = ((const float4*)x)[(row0 + li) * 16 + kc];
            } else {
                int ng = row0 + li;
                int bb = ng >> 9, n = ng & 511;
                size_t base = (((size_t)bb * HH) * NN + n) * CC + kc * 4;
                float4 p0 = *(const float4*)(part + base);
                float4 p1 = *(const float4*)(part + base + (size_t)NN * CC);
                float4 p2 = *(const float4*)(part + base + (size_t)2 * NN * CC);
                float4 p3 = *(const float4*)(part + base + (size_t)3 * NN * CC);
                float4 cbv = *(const float4*)(cbp + kc * 4);
                v.x = fmaxf(0.25f * (p0.x + p1.x + p2.x + p3.x) + cbv.x, 0.f);
                v.y = fmaxf(0.25f * (p0.y + p1.y + p2.y + p3.y) + cbv.y, 0.f);
                v.z = fmaxf(0.25f * (p0.z + p1.z + p2.z + p3.z) + cbv.z, 0.f);
                v.w = fmaxf(0.25f * (p0.w + p1.w + p2.w + p3.w) + cbv.w, 0.f);
            }
            s_x[kc*4+0][li] = v.x; s_x[kc*4+1][li] = v.y;
            s_x[kc*4+2][li] = v.z; s_x[kc*4+3][li] = v.w;
            float4 u = w4[(hh * 64 + li) * 16 + kc];
            s_w[kc*4+0][li] = u.x; s_w[kc*4+1][li] = u.y;
            s_w[kc*4+2][li] = u.z; s_w[kc*4+3][li] = u.w;
        }
    }
    __syncthreads();

    const int tx = t & 15, ty = t >> 4;
    float acc[4][4] = {};
    #pragma unroll
    for (int k = 0; k < 64; k++) {
        float4 a = *(const float4*)&s_x[k][ty * 4];
        float4 b = *(const float4*)&s_w[k][tx * 4];
        float av[4] = {a.x, a.y, a.z, a.w};
        float bv[4] = {b.x, b.y, b.z, b.w};
        #pragma unroll
        for (int i = 0; i < 4; i++)
            #pragma unroll
            for (int c = 0; c < 4; c++)
                acc[i][c] += av[i] * bv[c];
    }

    #pragma unroll
    for (int i = 0; i < 4; i++) {
        *(float4*)&g_h[(size_t)(row0 + ty * 4 + i) * 256 + hh * 64 + tx * 4] =
            make_float4(acc[i][0], acc[i][1], acc[i][2], acc[i][3]);
    }

    float aSv[4], aDv[4];
    #pragma unroll
    for (int c = 0; c < 4; c++) {
        aSv[c] = attS[hh * 64 + tx * 4 + c];
        aDv[c] = attD[hh * 64 + tx * 4 + c];
    }
    #pragma unroll
    for (int i = 0; i < 4; i++) {
        float ps = 0.f, pd = 0.f;
        #pragma unroll
        for (int c = 0; c < 4; c++) { ps += acc[i][c] * aSv[c]; pd += acc[i][c] * aDv[c]; }
        #pragma unroll
        for (int off = 8; off > 0; off >>= 1) {
            ps += __shfl_xor_sync(0xffffffffu, ps, off);
            pd += __shfl_xor_sync(0xffffffffu, pd, off);
        }
        if (tx == 0) {
            int ng = row0 + ty * 4 + i;
            int b = ng >> 9, n = ng & 511;
            g_asrc[(b * HH + hh) * NN + n] = ps;
            g_adst[(b * HH + hh) * NN + n] = pd;
        }
    }
}

// ---------------------------------------------------------------------------
// Kernel 2 (sorted-threshold GAT aggregation), one block per (b, h).
// exp(lrelu(d_i+s_j)) = [s_j >= -d_i] e^{d_i} e^{s_j}
//                     + [s_j <  -d_i] e^{.2 d_i} e^{.2 s_j}
// Sort s ascending with perm; chunk(8) sums of e^{s}h and e^{.2s}h; suffix /
// prefix scans over chunks; per-i: binary-searched split k_i, combine scan
// vectors + <=8 tail/head terms. All sums add-only.
// ---------------------------------------------------------------------------
extern __shared__ float agsm[];

__global__ __launch_bounds__(256) void k_agg()
{
    // smem layout (float offsets)
    float* s_s   = agsm;            // [512] sorted keys
    float* s_dd  = agsm + 512;      // [512]
    float* s_W1  = agsm + 1024;     // [512] e^{s}
    float* s_W2  = agsm + 1536;     // [512] e^{.2s}
    float* s_e1  = agsm + 2048;     // [512] e^{d}
    float* s_e2  = agsm + 2560;     // [512] e^{.2d}
    int*   s_pji = (int*)(agsm + 3072);  // [512] perm
    int*   s_k   = (int*)(agsm + 3584);  // [512] split index
    float* SUF1  = agsm + 4096;     // [66][64]
    float* PRE2  = agsm + 8320;     // [66][64]
    float* SUF1d = agsm + 12544;    // [66]
    float* PRE2d = agsm + 12610;    // [66]

    const int t = threadIdx.x;
    const int b = blockIdx.x;
    const int h = blockIdx.y;
    const int bh = b * HH + h;

    // phase 1: load s, d
    #pragma unroll
    for (int q = t; q < 512; q += 256) {
        s_s[q]  = g_asrc[bh * NN + q];
        s_pji[q] = q;
        s_dd[q] = g_adst[bh * NN + q];
    }
    __syncthreads();

    // phase 2: bitonic sort s ascending (payload = perm)
    for (int k = 2; k <= 512; k <<= 1) {
        for (int j = k >> 1; j > 0; j >>= 1) {
            int i = ((t & ~(j - 1)) << 1) | (t & (j - 1));
            int p = i | j;
            bool up = ((i & k) == 0);
            float ki = s_s[i], kp = s_s[p];
            if (up ? (ki > kp) : (ki < kp)) {
                s_s[i] = kp; s_s[p] = ki;
                int tmp = s_pji[i]; s_pji[i] = s_pji[p]; s_pji[p] = tmp;
            }
            __syncthreads();
        }
    }

    // phase 3: weights, exps, binary-searched split per i
    #pragma unroll
    for (int q = t; q < 512; q += 256) {
        float sv = s_s[q];
        s_W1[q] = __expf(sv);
        s_W2[q] = __expf(NEGS * sv);
        float dv = s_dd[q];
        s_e1[q] = __expf(dv);
        s_e2[q] = __expf(NEGS * dv);
        float thr = -dv;
        int lo = 0, hi = 512;
        while (lo < hi) {
            int mid = (lo + hi) >> 1;
            if (s_s[mid] < thr) lo = mid + 1; else hi = mid;
        }
        s_k[q] = lo;
    }
    __syncthreads();

    // phase 4: chunk sums (64 chunks of 8)
    {
        const int c = t & 63, mg = t >> 6;
        const float* hb = g_h + (size_t)(b * NN) * 256 + h * 64 + c;
        for (int m = mg; m < 64; m += 4) {
            float f1 = 0.f, f2 = 0.f;
            #pragma unroll
            for (int r = 0; r < 8; r++) {
                int jj = m * 8 + r;
                float hv = hb[(size_t)s_pji[jj] * 256];
                f1 += s_W1[jj] * hv;
                f2 += s_W2[jj] * hv;
            }
            SUF1[m * 64 + c] = f1;
            PRE2[(m + 1) * 64 + c] = f2;
        }
        if (t < 64) {
            int m = t;
            float f1 = 0.f, f2 = 0.f;
            #pragma unroll
            for (int r = 0; r < 8; r++) { f1 += s_W1[m*8+r]; f2 += s_W2[m*8+r]; }
            SUF1d[m] = f1;
            PRE2d[m + 1] = f2;
        }
    }
    __syncthreads();

    // phase 5: scans
    if (t < 64) {
        const int c = t;
        SUF1[64 * 64 + c] = 0.f; SUF1[65 * 64 + c] = 0.f;
        PRE2[c] = 0.f;
        float run = SUF1[63 * 64 + c];
        for (int m = 62; m >= 0; m--) { run += SUF1[m * 64 + c]; SUF1[m * 64 + c] = run; }
        float run2 = 0.f;
        for (int m = 1; m <= 64; m++) { run2 += PRE2[m * 64 + c]; PRE2[m * 64 + c] = run2; }
    } else if (t == 64) {
        SUF1d[64] = 0.f; SUF1d[65] = 0.f;
        float run = 0.f;
        for (int m = 63; m >= 0; m--) { run += SUF1d[m]; SUF1d[m] = run; }
    } else if (t == 65) {
        PRE2d[0] = 0.f;
        float run = 0.f;
        for (int m = 1; m <= 64; m++) { run += PRE2d[m]; PRE2d[m] = run; }
    }
    __syncthreads();

    // phase 6: emission
    {
        const int c = t & 63, ig = t >> 6;
        const float* hb = g_h + (size_t)(b * NN) * 256 + h * 64 + c;
        float* ob = g_part + ((size_t)bh * NN) * CC + c;
        for (int ii = ig; ii < 512; ii += 4) {
            int k = s_k[ii];
            int m = k >> 3, m8 = m << 3;
            float v1 = SUF1[(m + 1) * 64 + c];
            float d1 = SUF1d[m + 1];
            int jend = m8 + 8; if (jend > 512) jend = 512;
            for (int j = k; j < jend; j++) {
                float w = s_W1[j];
                v1 += w * hb[(size_t)s_pji[j] * 256];
                d1 += w;
            }
            float v2 = PRE2[m * 64 + c];
            float d2 = PRE2d[m];
            for (int j = m8; j < k; j++) {
                float w = s_W2[j];
                v2 += w * hb[(size_t)s_pji[j] * 256];
                d2 += w;
            }
            float e1 = s_e1[ii], e2 = s_e2[ii];
            float num = e1 * v1 + e2 * v2;
            float den = e1 * d1 + e2 * d2;
            ob[(size_t)ii * CC] = num * __frcp_rn(den);
        }
    }
}

// ---------------------------------------------------------------------------
// Kernel 3: head-combine + node-mean pooling + readout linear.
// ---------------------------------------------------------------------------
__global__ __launch_bounds__(256) void k_read(
    const float* __restrict__ rw, const float* __restrict__ rb,
    const float* __restrict__ cb2, float* __restrict__ out)
{
    __shared__ float s_part[4][64];
    __shared__ float s_pool[64];
    const int t = threadIdx.x;
    const int b = blockIdx.x;
    const int c = t & 63, pg = t >> 6;
    const float bias = cb2[c];
    float s = 0.f;
    for (int i = pg; i < NN; i += 4) {
        size_t base = (((size_t)b * HH) * NN + i) * CC + c;
        float v = g_part[base] + g_part[base + (size_t)NN * CC]
                + g_part[base + (size_t)2 * NN * CC]
                + g_part[base + (size_t)3 * NN * CC];
        s += fmaxf(0.25f * v + bias, 0.f);
    }
    s_part[pg][c] = s;
    __syncthreads();
    if (t < 64)
        s_pool[t] = (s_part[0][t] + s_part[1][t] + s_part[2][t] + s_part[3][t])
                    * (1.0f / NN);
    __syncthreads();
    if (t < 64) {
        float a = rb[t];
        #pragma unroll 8
        for (int c2 = 0; c2 < 64; c2++)
            a += s_pool[c2] * rw[t * 64 + c2];
        out[b * 64 + t] = a;
    }
}

// ---------------------------------------------------------------------------
extern "C" void kernel_launch(void* const* d_in, const int* in_sizes, int n_in,
                              void* d_out, int out_size)
{
    const float* emb = (const float*)d_in[0];
    const float* lin = (const float*)d_in[1];
    const float* aS  = (const float*)d_in[2];
    const float* aD  = (const float*)d_in[3];
    const float* cb  = (const float*)d_in[4];
    const float* rw  = (const float*)d_in[5];
    const float* rb  = (const float*)d_in[6];
    float* out = (float*)d_out;

    float* gpart = nullptr;
    cudaGetSymbolAddress((void**)&gpart, g_part);

    const int AG_SMEM = 12676 * 4;   // 50704 B
    cudaFuncSetAttribute(k_agg, cudaFuncAttributeMaxDynamicSharedMemorySize, AG_SMEM);

    for (int l = 0; l < 3; l++) {
        const float* cbp = (l == 0) ? nullptr : (cb + (l - 1) * CC);
        k_lin<<<dim3(512, 4), 256>>>(emb, gpart, lin + l * 256 * 64,
                                     aS + l * HH * CC, aD + l * HH * CC, cbp);
        k_agg<<<dim3(64, 4), 256, AG_SMEM>>>();
    }
    k_read<<<64, 256>>>(rw, rb, cb + 2 * CC, out);
}

// round 7
// speedup vs baseline: 5.4368x; 2.0878x over previous
#include <cuda_runtime.h>
#include <cstdint>

#define BB 64
#define NN 512
#define DD 64
#define HH 4
#define CC 64
#define NEGS 0.2f

// Scratch (device globals - no runtime allocation allowed)
__device__ float g_h[BB*NN*HH*CC];          // [b][n][h*64+c]
__device__ float g_x[BB*NN*DD];             // layer activations
__device__ float g_asrc[BB*HH*NN];          // [b][h][n]
__device__ float g_adst[BB*HH*NN];          // [b][h][n]
__device__ float g_S1f[BB*HH*520*CC];       // full suffix sums  (e^{s} h)
__device__ float g_P2f[BB*HH*520*CC];       // full prefix sums  (e^{.2s} h)
__device__ float g_r1[BB*HH*NN];            // 0.25*e^{d}/den per i
__device__ float g_r2[BB*HH*NN];            // 0.25*e^{.2d}/den per i
__device__ int   g_k[BB*HH*NN];             // split index per i

// ---------------------------------------------------------------------------
// Kernel 1: h = x @ W^T for one layer, 64x64 tile, one head per blockIdx.y.
// Epilogue computes a_src/a_dst per node.
// ---------------------------------------------------------------------------
__global__ __launch_bounds__(256) void k_lin(
    const float* __restrict__ x, const float* __restrict__ W,
    const float* __restrict__ attS, const float* __restrict__ attD)
{
    __shared__ float s_x[64][68];   // transposed [k][row]
    __shared__ float s_w[64][68];   // transposed [k][col]
    const int t    = threadIdx.x;
    const int row0 = blockIdx.x * 64;
    const int hh   = blockIdx.y;

    {
        const int li = t >> 2;
        const int c4 = t & 3;
        const float4* x4 = (const float4*)x;
        const float4* w4 = (const float4*)W;
        #pragma unroll
        for (int q = 0; q < 4; q++) {
            int kc = c4 + q * 4;
            float4 v = x4[(row0 + li) * 16 + kc];
            s_x[kc*4+0][li] = v.x; s_x[kc*4+1][li] = v.y;
            s_x[kc*4+2][li] = v.z; s_x[kc*4+3][li] = v.w;
            float4 u = w4[(hh * 64 + li) * 16 + kc];
            s_w[kc*4+0][li] = u.x; s_w[kc*4+1][li] = u.y;
            s_w[kc*4+2][li] = u.z; s_w[kc*4+3][li] = u.w;
        }
    }
    __syncthreads();

    const int tx = t & 15, ty = t >> 4;
    float acc[4][4] = {};
    #pragma unroll
    for (int k = 0; k < 64; k++) {
        float4 a = *(const float4*)&s_x[k][ty * 4];
        float4 b = *(const float4*)&s_w[k][tx * 4];
        float av[4] = {a.x, a.y, a.z, a.w};
        float bv[4] = {b.x, b.y, b.z, b.w};
        #pragma unroll
        for (int i = 0; i < 4; i++)
            #pragma unroll
            for (int c = 0; c < 4; c++)
                acc[i][c] += av[i] * bv[c];
    }

    #pragma unroll
    for (int i = 0; i < 4; i++) {
        *(float4*)&g_h[(size_t)(row0 + ty * 4 + i) * 256 + hh * 64 + tx * 4] =
            make_float4(acc[i][0], acc[i][1], acc[i][2], acc[i][3]);
    }

    float aSv[4], aDv[4];
    #pragma unroll
    for (int c = 0; c < 4; c++) {
        aSv[c] = attS[hh * 64 + tx * 4 + c];
        aDv[c] = attD[hh * 64 + tx * 4 + c];
    }
    #pragma unroll
    for (int i = 0; i < 4; i++) {
        float ps = 0.f, pd = 0.f;
        #pragma unroll
        for (int c = 0; c < 4; c++) { ps += acc[i][c] * aSv[c]; pd += acc[i][c] * aDv[c]; }
        #pragma unroll
        for (int off = 8; off > 0; off >>= 1) {
            ps += __shfl_xor_sync(0xffffffffu, ps, off);
            pd += __shfl_xor_sync(0xffffffffu, pd, off);
        }
        if (tx == 0) {
            int ng = row0 + ty * 4 + i;
            int b = ng >> 9, n = ng & 511;
            g_asrc[(b * HH + hh) * NN + n] = ps;
            g_adst[(b * HH + hh) * NN + n] = pd;
        }
    }
}

// ---------------------------------------------------------------------------
// Kernel 2a (k_prep): per (b,h): sort s; chunk(8) sums + chunk scans; then
// full per-position suffix/prefix arrays S1f/P2f written to global; scalar
// full arrays kept in smem to compute per-i r1/r2 (0.25*e/den) and k.
// All sums add-only.
// smem (floats): s_s[512] dd[512] W1[512] W2[512] perm[512i]
//   CH1[66*64] CH2[66*64] CH1d[66] CH2d[66] s1d[520] p2d[520]
// ---------------------------------------------------------------------------
extern __shared__ float psm[];

__global__ __launch_bounds__(256) void k_prep()
{
    float* s_s  = psm;              // 512
    float* s_dd = psm + 512;
    float* s_W1 = psm + 1024;
    float* s_W2 = psm + 1536;
    int*   s_pj = (int*)(psm + 2048);
    float* CH1  = psm + 2560;       // [66][64]
    float* CH2  = psm + 6784;       // [66][64]
    float* CH1d = psm + 11008;      // [66]
    float* CH2d = psm + 11074;      // [66]
    float* s1d  = psm + 11140;      // [520]
    float* p2d  = psm + 11660;      // [520]  -> total 12180 floats

    const int t = threadIdx.x;
    const int b = blockIdx.x;
    const int h = blockIdx.y;
    const int bh = b * HH + h;

    // phase 1: load
    #pragma unroll
    for (int q = t; q < 512; q += 256) {
        s_s[q]  = g_asrc[bh * NN + q];
        s_pj[q] = q;
        s_dd[q] = g_adst[bh * NN + q];
    }
    __syncthreads();

    // phase 2: bitonic sort ascending (payload perm)
    for (int k = 2; k <= 512; k <<= 1) {
        for (int j = k >> 1; j > 0; j >>= 1) {
            int i = ((t & ~(j - 1)) << 1) | (t & (j - 1));
            int p = i | j;
            bool up = ((i & k) == 0);
            float ki = s_s[i], kp = s_s[p];
            if (up ? (ki > kp) : (ki < kp)) {
                s_s[i] = kp; s_s[p] = ki;
                int tmp = s_pj[i]; s_pj[i] = s_pj[p]; s_pj[p] = tmp;
            }
            __syncthreads();
        }
    }

    // phase 3: sorted weights + per-i split (regs)
    int k_reg[2];
    #pragma unroll
    for (int pp = 0; pp < 2; pp++) {
        int q = t + pp * 256;
        float sv = s_s[q];
        s_W1[q] = __expf(sv);
        s_W2[q] = __expf(NEGS * sv);
        float thr = -s_dd[q];
        int lo = 0, hi = 512;
        while (lo < hi) {
            int mid = (lo + hi) >> 1;
            if (s_s[mid] < thr) lo = mid + 1; else hi = mid;
        }
        k_reg[pp] = lo;
    }
    __syncthreads();

    const float* hb = g_h + (size_t)(b * NN) * 256 + h * 64;

    // phase 4: chunk sums
    for (int p = t; p < 4096; p += 256) {
        int m = p >> 6, c = p & 63;
        float f1 = 0.f, f2 = 0.f;
        #pragma unroll
        for (int r = 0; r < 8; r++) {
            int jj = m * 8 + r;
            float hv = hb[(size_t)s_pj[jj] * 256 + c];
            f1 += s_W1[jj] * hv;
            f2 += s_W2[jj] * hv;
        }
        CH1[m * 64 + c] = f1;
        CH2[(m + 1) * 64 + c] = f2;
    }
    if (t < 64) {
        int m = t;
        float f1 = 0.f, f2 = 0.f;
        #pragma unroll
        for (int r = 0; r < 8; r++) { f1 += s_W1[m*8+r]; f2 += s_W2[m*8+r]; }
        CH1d[m] = f1;
        CH2d[m + 1] = f2;
    }
    __syncthreads();

    // phase 5: chunk scans
    if (t < 64) {
        const int c = t;
        CH1[64 * 64 + c] = 0.f;
        CH2[c] = 0.f;
        float run = 0.f;
        for (int m = 63; m >= 0; m--) { run += CH1[m * 64 + c]; CH1[m * 64 + c] = run; }
        float run2 = 0.f;
        for (int m = 1; m <= 64; m++) { run2 += CH2[m * 64 + c]; CH2[m * 64 + c] = run2; }
    } else if (t == 64) {
        CH1d[64] = 0.f;
        float run = 0.f;
        for (int m = 63; m >= 0; m--) { run += CH1d[m]; CH1d[m] = run; }
    } else if (t == 65) {
        CH2d[0] = 0.f;
        float run = 0.f;
        for (int m = 1; m <= 64; m++) { run += CH2d[m]; CH2d[m] = run; }
    }
    __syncthreads();

    // phase 6: full per-position arrays (global) + scalar full arrays (smem)
    {
        float* S1 = g_S1f + (size_t)bh * 520 * 64;
        float* P2 = g_P2f + (size_t)bh * 520 * 64;
        for (int p = t; p < 4096; p += 256) {
            int m = p >> 6, c = p & 63;
            float hv[8];
            #pragma unroll
            for (int r = 0; r < 8; r++)
                hv[r] = hb[(size_t)s_pj[m * 8 + r] * 256 + c];
            float run1 = CH1[(m + 1) * 64 + c];
            #pragma unroll
            for (int r = 7; r >= 0; r--) {
                run1 += s_W1[m * 8 + r] * hv[r];
                S1[(size_t)(m * 8 + r) * 64 + c] = run1;
            }
            float run2 = CH2[m * 64 + c];
            #pragma unroll
            for (int r = 0; r < 8; r++) {
                P2[(size_t)(m * 8 + r) * 64 + c] = run2;
                run2 += s_W2[m * 8 + r] * hv[r];
            }
        }
        if (t < 64) {
            int m = t;
            float run1 = CH1d[m + 1];
            #pragma unroll
            for (int r = 7; r >= 0; r--) { run1 += s_W1[m*8+r]; s1d[m*8+r] = run1; }
            float run2 = CH2d[m];
            #pragma unroll
            for (int r = 0; r < 8; r++) { p2d[m*8+r] = run2; run2 += s_W2[m*8+r]; }
        }
        // row 512 (k == 512 possible)
        if (t < 64) {
            S1[(size_t)512 * 64 + t] = 0.f;
            P2[(size_t)512 * 64 + t] = CH2[64 * 64 + t];
        }
        if (t == 64) { s1d[512] = 0.f; p2d[512] = CH2d[64]; }
    }
    __syncthreads();

    // phase 7: per-i scalars r1, r2, k
    #pragma unroll
    for (int pp = 0; pp < 2; pp++) {
        int q = t + pp * 256;
        float dv = s_dd[q];
        float e1 = __expf(dv);
        float e2 = __expf(NEGS * dv);
        int k = k_reg[pp];
        float den = e1 * s1d[k] + e2 * p2d[k];
        float inv = 0.25f * __frcp_rn(den);
        int gi = bh * NN + q;
        g_r1[gi] = e1 * inv;
        g_r2[gi] = e2 * inv;
        g_k[gi]  = k;
    }
}

// ---------------------------------------------------------------------------
// Kernel 2b (k_emit): per (b, i-slice of 64): for each (i,c):
//   x[b,i,c] = relu( sum_h (r1*S1f[k][c] + r2*P2f[k][c]) + bias[c] )
// 2 coalesced loads + 2 FMA per (i,c,h); head combine fused.
// ---------------------------------------------------------------------------
__global__ __launch_bounds__(256) void k_emit(const float* __restrict__ cb)
{
    __shared__ float s_r1[4][64], s_r2[4][64];
    __shared__ int   s_kk[4][64];
    const int t  = threadIdx.x;
    const int b  = blockIdx.x;
    const int i0 = blockIdx.y * 64;

    {
        const int h = t >> 6, ii = t & 63;
        const int idx = (b * HH + h) * NN + i0 + ii;
        s_r1[h][ii] = g_r1[idx];
        s_r2[h][ii] = g_r2[idx];
        s_kk[h][ii] = g_k[idx];
    }
    __syncthreads();

    const int c  = t & 63;
    const int ig = t >> 6;
    const float bias = cb[c];
    const size_t hb0 = (size_t)(b * HH) * 520 * 64;

    for (int ii = ig; ii < 64; ii += 4) {
        float acc = bias;
        #pragma unroll
        for (int h = 0; h < HH; h++) {
            const size_t base = hb0 + ((size_t)h * 520 + s_kk[h][ii]) * 64 + c;
            acc += s_r1[h][ii] * g_S1f[base] + s_r2[h][ii] * g_P2f[base];
        }
        g_x[(size_t)(b * NN + i0 + ii) * DD + c] = fmaxf(acc, 0.f);
    }
}

// ---------------------------------------------------------------------------
// Kernel 3: node-mean pooling + readout linear.
// ---------------------------------------------------------------------------
__global__ __launch_bounds__(256) void k_read(
    const float* __restrict__ rw, const float* __restrict__ rb,
    float* __restrict__ out)
{
    __shared__ float s_part[4][64];
    __shared__ float s_pool[64];
    const int t = threadIdx.x;
    const int b = blockIdx.x;
    const int c = t & 63, pg = t >> 6;
    float s = 0.f;
    for (int i = pg; i < NN; i += 4)
        s += g_x[(size_t)(b * NN + i) * DD + c];
    s_part[pg][c] = s;
    __syncthreads();
    if (t < 64)
        s_pool[t] = (s_part[0][t] + s_part[1][t] + s_part[2][t] + s_part[3][t])
                    * (1.0f / NN);
    __syncthreads();
    if (t < 64) {
        float a = rb[t];
        #pragma unroll 8
        for (int c2 = 0; c2 < 64; c2++)
            a += s_pool[c2] * rw[t * 64 + c2];
        out[b * 64 + t] = a;
    }
}

// ---------------------------------------------------------------------------
extern "C" void kernel_launch(void* const* d_in, const int* in_sizes, int n_in,
                              void* d_out, int out_size)
{
    const float* emb = (const float*)d_in[0];
    const float* lin = (const float*)d_in[1];
    const float* aS  = (const float*)d_in[2];
    const float* aD  = (const float*)d_in[3];
    const float* cb  = (const float*)d_in[4];
    const float* rw  = (const float*)d_in[5];
    const float* rb  = (const float*)d_in[6];
    float* out = (float*)d_out;

    float* gx = nullptr;
    cudaGetSymbolAddress((void**)&gx, g_x);

    const int PREP_SMEM = 12180 * 4;   // 48720 B
    cudaFuncSetAttribute(k_prep, cudaFuncAttributeMaxDynamicSharedMemorySize, PREP_SMEM);

    for (int l = 0; l < 3; l++) {
        const float* xin = (l == 0) ? emb : gx;
        k_lin<<<dim3(512, 4), 256>>>(xin, lin + l * 256 * 64,
                                     aS + l * HH * CC, aD + l * HH * CC);
        k_prep<<<dim3(64, 4), 256, PREP_SMEM>>>();
        k_emit<<<dim3(64, 8), 256>>>(cb + l * CC);
    }
    k_read<<<64, 256>>>(rw, rb, out);
}

// round 8
// speedup vs baseline: 5.5320x; 1.0175x over previous
#include <cuda_runtime.h>
#include <cstdint>

#define BB 64
#define NN 512
#define DD 64
#define HH 4
#define CC 64
#define NEGS 0.2f

typedef unsigned long long ull;

// Scratch (device globals - no runtime allocation allowed)
__device__ float g_h[BB*NN*HH*CC];          // [b][n][h*64+c]
__device__ float g_x[BB*NN*DD];             // layer activations
__device__ float g_asrc[BB*HH*NN];          // [b][h][n]
__device__ float g_adst[BB*HH*NN];          // [b][h][n]
__device__ float g_S1f[BB*HH*520*CC];       // full suffix sums  (e^{s} h)
__device__ float g_P2f[BB*HH*520*CC];       // full prefix sums  (e^{.2s} h)
__device__ float g_r1[BB*HH*NN];            // 0.25*e^{d}/den per i
__device__ float g_r2[BB*HH*NN];            // 0.25*e^{.2d}/den per i
__device__ int   g_k[BB*HH*NN];             // split index per i

// ---- f32x2 helpers -------------------------------------------------------
__device__ __forceinline__ ull packdup(float a) {
    ull r; asm("mov.b64 %0, {%1, %1};" : "=l"(r) : "f"(a)); return r;
}
__device__ __forceinline__ void fma2(ull& d, ull a, ull b) {
    asm("fma.rn.f32x2 %0, %1, %2, %0;" : "+l"(d) : "l"(a), "l"(b));
}
__device__ __forceinline__ float2 unpack2(ull v) {
    float2 r; asm("mov.b64 {%0, %1}, %2;" : "=f"(r.x), "=f"(r.y) : "l"(v));
    return r;
}

// ---------------------------------------------------------------------------
// Kernel 1: h = x @ W^T, 128 rows x 64 cols per block (one head), 128 threads,
// microtile 8i x 8c with f32x2 FMA. Epilogue: g_h write + a_src/a_dst.
// dyn smem: s_x[64][128] (32KB) + s_w[64][72] (18KB) = 51200 B
// ---------------------------------------------------------------------------
extern __shared__ float linsm[];

__global__ __launch_bounds__(128) void k_lin(
    const float* __restrict__ x, const float* __restrict__ W,
    const float* __restrict__ attS, const float* __restrict__ attD)
{
    float (*s_x)[128] = (float(*)[128])linsm;              // [k][row]
    float (*s_w)[72]  = (float(*)[72])(linsm + 64 * 128);  // [k][col]
    const int t    = threadIdx.x;
    const int row0 = blockIdx.x * 128;
    const int hh   = blockIdx.y;

    // stage x: thread t owns global row row0+t
    {
        const float4* x4 = (const float4*)x;
        #pragma unroll
        for (int kc = 0; kc < 16; kc++) {
            float4 v = x4[(row0 + t) * 16 + kc];
            s_x[kc*4+0][t] = v.x; s_x[kc*4+1][t] = v.y;
            s_x[kc*4+2][t] = v.z; s_x[kc*4+3][t] = v.w;
        }
        const float4* w4 = (const float4*)W;
        const int li = t >> 1;
        const int q0 = (t & 1) * 8;
        #pragma unroll
        for (int q = 0; q < 8; q++) {
            int kc = q0 + q;
            float4 u = w4[(hh * 64 + li) * 16 + kc];
            s_w[kc*4+0][li] = u.x; s_w[kc*4+1][li] = u.y;
            s_w[kc*4+2][li] = u.z; s_w[kc*4+3][li] = u.w;
        }
    }
    __syncthreads();

    const int tx = t & 7;    // c group (8 cols)
    const int ty = t >> 3;   // i group (8 rows), 0..15
    ull acc[32];
    #pragma unroll
    for (int k = 0; k < 32; k++) acc[k] = 0ull;

    #pragma unroll 4
    for (int k = 0; k < 64; k++) {
        float4 a0 = *(const float4*)&s_x[k][ty * 8];
        float4 a1 = *(const float4*)&s_x[k][ty * 8 + 4];
        ulonglong2 b0 = *(const ulonglong2*)&s_w[k][tx * 8];
        ulonglong2 b1 = *(const ulonglong2*)&s_w[k][tx * 8 + 4];
        ull bp[4] = {b0.x, b0.y, b1.x, b1.y};
        float av[8] = {a0.x, a0.y, a0.z, a0.w, a1.x, a1.y, a1.z, a1.w};
        #pragma unroll
        for (int i = 0; i < 8; i++) {
            ull ad = packdup(av[i]);
            #pragma unroll
            for (int c2 = 0; c2 < 4; c2++)
                fma2(acc[i * 4 + c2], ad, bp[c2]);
        }
    }

    // epilogue
    float aSv[8], aDv[8];
    #pragma unroll
    for (int c = 0; c < 8; c++) {
        aSv[c] = attS[hh * 64 + tx * 8 + c];
        aDv[c] = attD[hh * 64 + tx * 8 + c];
    }
    #pragma unroll
    for (int i = 0; i < 8; i++) {
        float v[8];
        #pragma unroll
        for (int c2 = 0; c2 < 4; c2++) {
            float2 f = unpack2(acc[i * 4 + c2]);
            v[c2 * 2] = f.x; v[c2 * 2 + 1] = f.y;
        }
        float* hp = g_h + (size_t)(row0 + ty * 8 + i) * 256 + hh * 64 + tx * 8;
        *(float4*)hp       = make_float4(v[0], v[1], v[2], v[3]);
        *(float4*)(hp + 4) = make_float4(v[4], v[5], v[6], v[7]);

        float ps = 0.f, pd = 0.f;
        #pragma unroll
        for (int c = 0; c < 8; c++) { ps += v[c] * aSv[c]; pd += v[c] * aDv[c]; }
        #pragma unroll
        for (int off = 4; off > 0; off >>= 1) {
            ps += __shfl_xor_sync(0xffffffffu, ps, off);
            pd += __shfl_xor_sync(0xffffffffu, pd, off);
        }
        if (tx == 0) {
            int ng = row0 + ty * 8 + i;
            int b = ng >> 9, n = ng & 511;
            g_asrc[(b * HH + hh) * NN + n] = ps;
            g_adst[(b * HH + hh) * NN + n] = pd;
        }
    }
}

// ---------------------------------------------------------------------------
// Kernel 2a (k_prep), 512 threads, one block per (b,h).
// Sort s; chunk(8) sums+scans; full per-position suffix/prefix arrays to
// global; per-i scalars r1/r2/k. Warp-local bitonic stages for j<=32;
// float2 gathers/stores in the heavy phases.
// ---------------------------------------------------------------------------
extern __shared__ float psm[];

__global__ __launch_bounds__(512) void k_prep()
{
    float* s_s  = psm;              // 512
    float* s_dd = psm + 512;
    float* s_W1 = psm + 1024;
    float* s_W2 = psm + 1536;
    int*   s_pj = (int*)(psm + 2048);
    float* CH1  = psm + 2560;       // [66][64]
    float* CH2  = psm + 6784;       // [66][64]
    float* CH1d = psm + 11008;      // [66]
    float* CH2d = psm + 11074;      // [66]
    float* s1d  = psm + 11140;      // [520]
    float* p2d  = psm + 11660;      // [520]  -> 12180 floats

    const int t = threadIdx.x;
    const int b = blockIdx.x;
    const int h = blockIdx.y;
    const int bh = b * HH + h;

    // phase 1: load (1 item/thread)
    s_s[t]  = g_asrc[bh * NN + t];
    s_pj[t] = t;
    s_dd[t] = g_adst[bh * NN + t];

    // phase 2: bitonic sort ascending; stages with j<=32 are warp-local
    {
        int prev_cross = 1;
        for (int k = 2; k <= 512; k <<= 1) {
            for (int j = k >> 1; j > 0; j >>= 1) {
                int cross = (j >= 64);
                if (cross | prev_cross) __syncthreads(); else __syncwarp();
                if (t < 256) {
                    int i = ((t & ~(j - 1)) << 1) | (t & (j - 1));
                    int p = i | j;
                    bool up = ((i & k) == 0);
                    float ki = s_s[i], kp = s_s[p];
                    if (up ? (ki > kp) : (ki < kp)) {
                        s_s[i] = kp; s_s[p] = ki;
                        int tmp = s_pj[i]; s_pj[i] = s_pj[p]; s_pj[p] = tmp;
                    }
                }
                prev_cross = cross;
            }
        }
        __syncthreads();
    }

    // phase 3: sorted weights + per-i split (1 item/thread)
    int k_reg;
    {
        float sv = s_s[t];
        s_W1[t] = __expf(sv);
        s_W2[t] = __expf(NEGS * sv);
        float thr = -s_dd[t];
        int lo = 0, hi = 512;
        while (lo < hi) {
            int mid = (lo + hi) >> 1;
            if (s_s[mid] < thr) lo = mid + 1; else hi = mid;
        }
        k_reg = lo;
    }
    __syncthreads();

    const float* hb = g_h + (size_t)(b * NN) * 256 + h * 64;

    // phase 4: chunk sums (float2): 2048 items (64 m x 32 c-pairs)
    #pragma unroll
    for (int p = t; p < 2048; p += 512) {
        int m = p >> 5, c = (p & 31) * 2;
        float2 f1 = make_float2(0.f, 0.f), f2 = make_float2(0.f, 0.f);
        #pragma unroll
        for (int r = 0; r < 8; r++) {
            int jj = m * 8 + r;
            float2 hv = *(const float2*)(hb + (size_t)s_pj[jj] * 256 + c);
            float w1 = s_W1[jj], w2 = s_W2[jj];
            f1.x += w1 * hv.x; f1.y += w1 * hv.y;
            f2.x += w2 * hv.x; f2.y += w2 * hv.y;
        }
        *(float2*)&CH1[m * 64 + c] = f1;
        *(float2*)&CH2[(m + 1) * 64 + c] = f2;
    }
    if (t < 64) {
        int m = t;
        float f1 = 0.f, f2 = 0.f;
        #pragma unroll
        for (int r = 0; r < 8; r++) { f1 += s_W1[m*8+r]; f2 += s_W2[m*8+r]; }
        CH1d[m] = f1;
        CH2d[m + 1] = f2;
    }
    __syncthreads();

    // phase 5: chunk scans (per-c serial over 64 chunks)
    if (t < 64) {
        const int c = t;
        CH1[64 * 64 + c] = 0.f;
        CH2[c] = 0.f;
        float run = 0.f;
        for (int m = 63; m >= 0; m--) { run += CH1[m * 64 + c]; CH1[m * 64 + c] = run; }
        float run2 = 0.f;
        for (int m = 1; m <= 64; m++) { run2 += CH2[m * 64 + c]; CH2[m * 64 + c] = run2; }
    } else if (t == 64) {
        CH1d[64] = 0.f;
        float run = 0.f;
        for (int m = 63; m >= 0; m--) { run += CH1d[m]; CH1d[m] = run; }
    } else if (t == 65) {
        CH2d[0] = 0.f;
        float run = 0.f;
        for (int m = 1; m <= 64; m++) { run += CH2d[m]; CH2d[m] = run; }
    }
    __syncthreads();

    // phase 6: full per-position arrays (float2 to global) + scalar arrays
    {
        float* S1 = g_S1f + (size_t)bh * 520 * 64;
        float* P2 = g_P2f + (size_t)bh * 520 * 64;
        #pragma unroll
        for (int p = t; p < 2048; p += 512) {
            int m = p >> 5, c = (p & 31) * 2;
            float2 hv[8];
            #pragma unroll
            for (int r = 0; r < 8; r++)
                hv[r] = *(const float2*)(hb + (size_t)s_pj[m * 8 + r] * 256 + c);
            float2 run1 = *(const float2*)&CH1[(m + 1) * 64 + c];
            #pragma unroll
            for (int r = 7; r >= 0; r--) {
                float w = s_W1[m * 8 + r];
                run1.x += w * hv[r].x; run1.y += w * hv[r].y;
                *(float2*)&S1[(size_t)(m * 8 + r) * 64 + c] = run1;
            }
            float2 run2 = *(const float2*)&CH2[m * 64 + c];
            #pragma unroll
            for (int r = 0; r < 8; r++) {
                *(float2*)&P2[(size_t)(m * 8 + r) * 64 + c] = run2;
                float w = s_W2[m * 8 + r];
                run2.x += w * hv[r].x; run2.y += w * hv[r].y;
            }
        }
        if (t < 64) {
            int m = t;
            float run1 = CH1d[m + 1];
            #pragma unroll
            for (int r = 7; r >= 0; r--) { run1 += s_W1[m*8+r]; s1d[m*8+r] = run1; }
            float run2 = CH2d[m];
            #pragma unroll
            for (int r = 0; r < 8; r++) { p2d[m*8+r] = run2; run2 += s_W2[m*8+r]; }
        }
        if (t < 64) {
            S1[(size_t)512 * 64 + t] = 0.f;
            P2[(size_t)512 * 64 + t] = CH2[64 * 64 + t];
        }
        if (t == 64) { s1d[512] = 0.f; p2d[512] = CH2d[64]; }
    }
    __syncthreads();

    // phase 7: per-i scalars (1 item/thread)
    {
        float dv = s_dd[t];
        float e1 = __expf(dv);
        float e2 = __expf(NEGS * dv);
        float den = e1 * s1d[k_reg] + e2 * p2d[k_reg];
        float inv = 0.25f * __frcp_rn(den);
        int gi = bh * NN + t;
        g_r1[gi] = e1 * inv;
        g_r2[gi] = e2 * inv;
        g_k[gi]  = k_reg;
    }
}

// ---------------------------------------------------------------------------
// Kernel 2b (k_emit): x[b,i,c] = relu( sum_h (r1*S1f[k][c]+r2*P2f[k][c]) + b )
// ---------------------------------------------------------------------------
__global__ __launch_bounds__(256) void k_emit(const float* __restrict__ cb)
{
    __shared__ float s_r1[4][64], s_r2[4][64];
    __shared__ int   s_kk[4][64];
    const int t  = threadIdx.x;
    const int b  = blockIdx.x;
    const int i0 = blockIdx.y * 64;

    {
        const int h = t >> 6, ii = t & 63;
        const int idx = (b * HH + h) * NN + i0 + ii;
        s_r1[h][ii] = g_r1[idx];
        s_r2[h][ii] = g_r2[idx];
        s_kk[h][ii] = g_k[idx];
    }
    __syncthreads();

    const int c  = t & 63;
    const int ig = t >> 6;
    const float bias = cb[c];
    const size_t hb0 = (size_t)(b * HH) * 520 * 64;

    for (int ii = ig; ii < 64; ii += 4) {
        float acc = bias;
        #pragma unroll
        for (int h = 0; h < HH; h++) {
            const size_t base = hb0 + ((size_t)h * 520 + s_kk[h][ii]) * 64 + c;
            acc += s_r1[h][ii] * g_S1f[base] + s_r2[h][ii] * g_P2f[base];
        }
        g_x[(size_t)(b * NN + i0 + ii) * DD + c] = fmaxf(acc, 0.f);
    }
}

// ---------------------------------------------------------------------------
// Kernel 3: node-mean pooling + readout linear.
// ---------------------------------------------------------------------------
__global__ __launch_bounds__(256) void k_read(
    const float* __restrict__ rw, const float* __restrict__ rb,
    float* __restrict__ out)
{
    __shared__ float s_part[4][64];
    __shared__ float s_pool[64];
    const int t = threadIdx.x;
    const int b = blockIdx.x;
    const int c = t & 63, pg = t >> 6;
    float s = 0.f;
    for (int i = pg; i < NN; i += 4)
        s += g_x[(size_t)(b * NN + i) * DD + c];
    s_part[pg][c] = s;
    __syncthreads();
    if (t < 64)
        s_pool[t] = (s_part[0][t] + s_part[1][t] + s_part[2][t] + s_part[3][t])
                    * (1.0f / NN);
    __syncthreads();
    if (t < 64) {
        float a = rb[t];
        #pragma unroll 8
        for (int c2 = 0; c2 < 64; c2++)
            a += s_pool[c2] * rw[t * 64 + c2];
        out[b * 64 + t] = a;
    }
}

// ---------------------------------------------------------------------------
extern "C" void kernel_launch(void* const* d_in, const int* in_sizes, int n_in,
                              void* d_out, int out_size)
{
    const float* emb = (const float*)d_in[0];
    const float* lin = (const float*)d_in[1];
    const float* aS  = (const float*)d_in[2];
    const float* aD  = (const float*)d_in[3];
    const float* cb  = (const float*)d_in[4];
    const float* rw  = (const float*)d_in[5];
    const float* rb  = (const float*)d_in[6];
    float* out = (float*)d_out;

    float* gx = nullptr;
    cudaGetSymbolAddress((void**)&gx, g_x);

    const int LIN_SMEM  = (64 * 128 + 64 * 72) * 4;  // 51200 B
    const int PREP_SMEM = 12180 * 4;                 // 48720 B
    cudaFuncSetAttribute(k_lin, cudaFuncAttributeMaxDynamicSharedMemorySize, LIN_SMEM);
    cudaFuncSetAttribute(k_prep, cudaFuncAttributeMaxDynamicSharedMemorySize, PREP_SMEM);

    for (int l = 0; l < 3; l++) {
        const float* xin = (l == 0) ? emb : gx;
        k_lin<<<dim3(256, 4), 128, LIN_SMEM>>>(xin, lin + l * 256 * 64,
                                               aS + l * HH * CC, aD + l * HH * CC);
        k_prep<<<dim3(64, 4), 512, PREP_SMEM>>>();
        k_emit<<<dim3(64, 8), 256>>>(cb + l * CC);
    }
    k_read<<<64, 256>>>(rw, rb, out);
}